// round 4
// baseline (speedup 1.0000x reference)
#include <cuda_runtime.h>

#define B_TOTAL 1024
#define N 128
#define MW 1.0f
#define NITERS 300
#define NROUNDS 10   // 3 bisection steps per round => 30 effective steps

// ---------- warp reductions via butterfly shuffles ----------
__device__ __forceinline__ float wsum(float v) {
#pragma unroll
    for (int m = 16; m >= 1; m >>= 1)
        v += __shfl_xor_sync(0xffffffffu, v, m);
    return v;
}
__device__ __forceinline__ float wmin(float v) {
#pragma unroll
    for (int m = 16; m >= 1; m >>= 1)
        v = fminf(v, __shfl_xor_sync(0xffffffffu, v, m));
    return v;
}
__device__ __forceinline__ float wmax(float v) {
#pragma unroll
    for (int m = 16; m >= 1; m >>= 1)
        v = fmaxf(v, __shfl_xor_sync(0xffffffffu, v, m));
    return v;
}
// reduce 7 independent sums together (chains pipeline through the SHFL unit)
__device__ __forceinline__ void wsum7(float s[7]) {
#pragma unroll
    for (int m = 16; m >= 1; m >>= 1) {
#pragma unroll
        for (int k = 0; k < 7; ++k)
            s[k] += __shfl_xor_sync(0xffffffffu, s[k], m);
    }
}

__device__ __forceinline__ float clip01m(float z) {
    return fminf(fmaxf(z, 0.0f), MW);
}
__device__ __forceinline__ float clip4sum(float4 v, float t) {
    float s = clip01m(v.x - t);
    s += clip01m(v.y - t);
    s += clip01m(v.z - t);
    s += clip01m(v.w - t);
    return s;
}

__global__ __launch_bounds__(128, 3)
void markowitz_kernel(const float* __restrict__ rets,
                      const float* __restrict__ cov,
                      const float* __restrict__ gamma_sqrt,
                      const float* __restrict__ alpha,
                      float* __restrict__ out)
{
    __shared__ __align__(16) float ysh[2][N];
    __shared__ __align__(16) float vsh[N];
    __shared__ float red[4];

    const int b = blockIdx.x;
    const int i = threadIdx.x;
    const int lane = i & 31;

    const float* __restrict__ Cb = cov + (size_t)b * (N * N);

    // ---------------- Phase A: Q = g^2 * C^T C + |alpha| I ----------------
    float q[N];
#pragma unroll
    for (int j = 0; j < N; ++j) q[j] = 0.0f;

#pragma unroll 1
    for (int k = 0; k < N; ++k) {
        const float c = Cb[k * N + i];                       // coalesced across threads
        const float4* __restrict__ rk = (const float4*)(Cb + k * N);  // broadcast
#pragma unroll
        for (int j4 = 0; j4 < N / 4; ++j4) {
            float4 r4 = rk[j4];
            q[4 * j4 + 0] += c * r4.x;
            q[4 * j4 + 1] += c * r4.y;
            q[4 * j4 + 2] += c * r4.z;
            q[4 * j4 + 3] += c * r4.w;
        }
    }

    const float g = gamma_sqrt[b];
    const float g2 = g * g;
    const float a = fabsf(alpha[b]);

#pragma unroll
    for (int j = 0; j < N; ++j) q[j] *= g2;
    q[i] += a;   // diagonal

    // Frobenius norm of Q -> step = 1/(2*||Q||_F)
    float fro = 0.0f;
#pragma unroll
    for (int j = 0; j < N; ++j) fro += q[j] * q[j];
    fro = wsum(fro);
    if (lane == 0) red[i >> 5] = fro;
    __syncthreads();
    const float totF = (red[0] + red[1]) + (red[2] + red[3]);
    const float step = 1.0f / (2.0f * sqrtf(totF));

    // Fold: qs = 2*step*Q, rs = step*rets
    const float two_step = 2.0f * step;
#pragma unroll
    for (int j = 0; j < N; ++j) q[j] *= two_step;
    const float rs = step * rets[(size_t)b * N + i];

    // ---------------- Phase B: FISTA ----------------
    float w = 1.0f / (float)N;
    float y = w;
    float t = 1.0f;
    int buf = 0;
    ysh[0][i] = y;
    __syncthreads();

#pragma unroll 1
    for (int it = 0; it < NITERS; ++it) {
        // grad step: v = y - (2*step*Q) y + step*rets
        const float4* __restrict__ yv4 = (const float4*)ysh[buf];
        float a0 = 0.f, a1 = 0.f, a2 = 0.f, a3 = 0.f;
#pragma unroll
        for (int j4 = 0; j4 < N / 4; ++j4) {
            float4 yv = yv4[j4];
            a0 += q[4 * j4 + 0] * yv.x;
            a1 += q[4 * j4 + 1] * yv.y;
            a2 += q[4 * j4 + 2] * yv.z;
            a3 += q[4 * j4 + 3] * yv.w;
        }
        const float v = y - ((a0 + a1) + (a2 + a3)) + rs;
        vsh[i] = v;
        __syncthreads();

        // Warp-redundant capped-simplex projection (no barriers inside)
        const float4 vv = ((const float4*)vsh)[lane];

        float mn = fminf(fminf(vv.x, vv.y), fminf(vv.z, vv.w));
        float mx = fmaxf(fmaxf(vv.x, vv.y), fmaxf(vv.z, vv.w));
        mn = wmin(mn);
        mx = wmax(mx);
        float lo = mn - MW;
        float hi = mx;

        // 3 exact reference bisection steps per round via a 7-tau midpoint tree
#pragma unroll 1
        for (int r = 0; r < NROUNDS; ++r) {
            const float t4 = 0.5f * (lo + hi);
            const float t2 = 0.5f * (lo + t4);
            const float t6 = 0.5f * (t4 + hi);
            const float t1 = 0.5f * (lo + t2);
            const float t3 = 0.5f * (t2 + t4);
            const float t5 = 0.5f * (t4 + t6);
            const float t7 = 0.5f * (t6 + hi);
            float s[7];
            s[0] = clip4sum(vv, t1);
            s[1] = clip4sum(vv, t2);
            s[2] = clip4sum(vv, t3);
            s[3] = clip4sum(vv, t4);
            s[4] = clip4sum(vv, t5);
            s[5] = clip4sum(vv, t6);
            s[6] = clip4sum(vv, t7);
            wsum7(s);
            // decision tree == three sequential reference bisection steps
            if (s[3] > 1.0f) {            // step 1: lo = t4
                if (s[5] > 1.0f) {        // step 2: lo = t6
                    if (s[6] > 1.0f) { lo = t7; }          // step 3
                    else             { lo = t6; hi = t7; }
                } else {                  // step 2: hi = t6
                    if (s[4] > 1.0f) { lo = t5; hi = t6; }
                    else             { lo = t4; hi = t5; }
                }
            } else {                      // step 1: hi = t4
                if (s[1] > 1.0f) {        // step 2: lo = t2
                    if (s[2] > 1.0f) { lo = t3; hi = t4; }
                    else             { lo = t2; hi = t3; }
                } else {                  // step 2: hi = t2
                    if (s[0] > 1.0f) { lo = t1; hi = t2; }
                    else             { hi = t1; }
                }
            }
        }
        const float tau0 = 0.5f * (lo + hi);

        // Active-set classification + differentiable-tau re-derivation
        float sfree = 0.f, cfree = 0.f, cup = 0.f;
        {
            float z;
            z = vv.x - tau0;
            if (z > 0.f && z < MW) { sfree += vv.x; cfree += 1.f; } else if (z >= MW) cup += 1.f;
            z = vv.y - tau0;
            if (z > 0.f && z < MW) { sfree += vv.y; cfree += 1.f; } else if (z >= MW) cup += 1.f;
            z = vv.z - tau0;
            if (z > 0.f && z < MW) { sfree += vv.z; cfree += 1.f; } else if (z >= MW) cup += 1.f;
            z = vv.w - tau0;
            if (z > 0.f && z < MW) { sfree += vv.w; cfree += 1.f; } else if (z >= MW) cup += 1.f;
        }
        // three independent sums — interleave the butterflies
#pragma unroll
        for (int m = 16; m >= 1; m >>= 1) {
            sfree += __shfl_xor_sync(0xffffffffu, sfree, m);
            cfree += __shfl_xor_sync(0xffffffffu, cfree, m);
            cup   += __shfl_xor_sync(0xffffffffu, cup,   m);
        }
        const float nfree = fmaxf(cfree, 1.0f);
        const float tau = (sfree + MW * cup - 1.0f) / nfree;

        // own-element update (identical arithmetic to the redundant pass)
        const float z = v - tau0;
        const bool fr = (z > 0.0f) && (z < MW);
        const bool up = (z >= MW);
        const float wn = fr ? (v - tau) : (up ? MW : 0.0f);

        const float tn = 0.5f * (1.0f + sqrtf(1.0f + 4.0f * t * t));
        const float yn = wn + ((t - 1.0f) / tn) * (wn - w);
        w = wn;
        y = yn;
        t = tn;

        buf ^= 1;
        ysh[buf][i] = yn;
        __syncthreads();
    }

    out[(size_t)b * N + i] = w;
}

extern "C" void kernel_launch(void* const* d_in, const int* in_sizes, int n_in,
                              void* d_out, int out_size) {
    const float* rets  = (const float*)d_in[0];
    const float* cov   = (const float*)d_in[1];
    const float* gamma = (const float*)d_in[2];
    const float* alpha = (const float*)d_in[3];
    float* out = (float*)d_out;
    (void)in_sizes; (void)n_in; (void)out_size;

    markowitz_kernel<<<B_TOTAL, N>>>(rets, cov, gamma, alpha, out);
}

// round 6
// speedup vs baseline: 2.0392x; 2.0392x over previous
#include <cuda_runtime.h>

#define B_TOTAL 1024
#define N 128
#define MW 1.0f
#define NITERS 300
#define MAX_EVALS 40

// ---------- warp reductions via butterfly shuffles ----------
__device__ __forceinline__ float wsum(float v) {
#pragma unroll
    for (int m = 16; m >= 1; m >>= 1)
        v += __shfl_xor_sync(0xffffffffu, v, m);
    return v;
}

__global__ __launch_bounds__(128, 3)
void markowitz_kernel(const float* __restrict__ rets,
                      const float* __restrict__ cov,
                      const float* __restrict__ gamma_sqrt,
                      const float* __restrict__ alpha,
                      float* __restrict__ out)
{
    __shared__ __align__(16) float ysh[2][N];
    __shared__ __align__(16) float vsh[N];
    __shared__ float red[4];

    const int b = blockIdx.x;
    const int i = threadIdx.x;
    const int lane = i & 31;

    const float* __restrict__ Cb = cov + (size_t)b * (N * N);

    // ---------------- Phase A: Q = g^2 * C^T C + |alpha| I ----------------
    float q[N];
#pragma unroll
    for (int j = 0; j < N; ++j) q[j] = 0.0f;

#pragma unroll 1
    for (int k = 0; k < N; ++k) {
        const float c = Cb[k * N + i];                        // coalesced
        const float4* __restrict__ rk = (const float4*)(Cb + k * N);  // broadcast
#pragma unroll
        for (int j4 = 0; j4 < N / 4; ++j4) {
            float4 r4 = rk[j4];
            q[4 * j4 + 0] += c * r4.x;
            q[4 * j4 + 1] += c * r4.y;
            q[4 * j4 + 2] += c * r4.z;
            q[4 * j4 + 3] += c * r4.w;
        }
    }

    const float g = gamma_sqrt[b];
    const float g2 = g * g;
    const float a = fabsf(alpha[b]);

#pragma unroll
    for (int j = 0; j < N; ++j) q[j] *= g2;
    q[i] += a;   // diagonal

    // Frobenius norm of Q -> step = 1/(2*||Q||_F)
    float fro = 0.0f;
#pragma unroll
    for (int j = 0; j < N; ++j) fro += q[j] * q[j];
    fro = wsum(fro);
    if (lane == 0) red[i >> 5] = fro;
    __syncthreads();
    const float totF = (red[0] + red[1]) + (red[2] + red[3]);
    const float step = 1.0f / (2.0f * sqrtf(totF));

    // Fold: qs = 2*step*Q, rs = step*rets
    const float two_step = 2.0f * step;
#pragma unroll
    for (int j = 0; j < N; ++j) q[j] *= two_step;
    const float rs = step * rets[(size_t)b * N + i];

    // ---------------- Phase B: FISTA ----------------
    float w = 1.0f / (float)N;
    float y = w;
    float t = 1.0f;
    float tau_prev = 0.0f;    // warm start for Newton (uniform across warp)
    int buf = 0;
    ysh[0][i] = y;
    __syncthreads();

#pragma unroll 1
    for (int it = 0; it < NITERS; ++it) {
        // grad step: v = y - (2*step*Q) y + step*rets
        const float4* __restrict__ yv4 = (const float4*)ysh[buf];
        float a0 = 0.f, a1 = 0.f, a2 = 0.f, a3 = 0.f;
#pragma unroll
        for (int j4 = 0; j4 < N / 4; ++j4) {
            float4 yv = yv4[j4];
            a0 += q[4 * j4 + 0] * yv.x;
            a1 += q[4 * j4 + 1] * yv.y;
            a2 += q[4 * j4 + 2] * yv.z;
            a3 += q[4 * j4 + 3] * yv.w;
        }
        const float v = y - ((a0 + a1) + (a2 + a3)) + rs;
        vsh[i] = v;
        __syncthreads();

        // -------- warp-redundant capped-simplex projection (Newton) --------
        const float4 vv = ((const float4*)vsh)[lane];

        // bracket = [min(v)-MW, max(v)]  (matches reference)
        float mn = fminf(fminf(vv.x, vv.y), fminf(vv.z, vv.w));
        float mx = fmaxf(fmaxf(vv.x, vv.y), fmaxf(vv.z, vv.w));
#pragma unroll
        for (int m = 16; m >= 1; m >>= 1) {
            mn = fminf(mn, __shfl_xor_sync(0xffffffffu, mn, m));
            mx = fmaxf(mx, __shfl_xor_sync(0xffffffffu, mx, m));
        }
        float lo = mn - MW;
        float hi = mx;
        const float eps = 1e-6f * (hi - lo);

        // warm start (all Newton state is lane-uniform -> uniform branches)
        float tau = (tau_prev > lo && tau_prev < hi) ? tau_prev : 0.5f * (lo + hi);

#pragma unroll 1
        for (int e = 0; e < MAX_EVALS; ++e) {
            // s(tau) = sum saturate(v - tau);  slope count = #{0<z<1}
            const float z0 = __saturatef(vv.x - tau);
            const float z1 = __saturatef(vv.y - tau);
            const float z2 = __saturatef(vv.z - tau);
            const float z3 = __saturatef(vv.w - tau);
            float s = (z0 + z1) + (z2 + z3);
            float c = ((z0 > 0.f && z0 < 1.f) ? 1.f : 0.f)
                    + ((z1 > 0.f && z1 < 1.f) ? 1.f : 0.f)
                    + ((z2 > 0.f && z2 < 1.f) ? 1.f : 0.f)
                    + ((z3 > 0.f && z3 < 1.f) ? 1.f : 0.f);
#pragma unroll
            for (int m = 16; m >= 1; m >>= 1) {
                s += __shfl_xor_sync(0xffffffffu, s, m);
                c += __shfl_xor_sync(0xffffffffu, c, m);
            }
            if (s > 1.0f) lo = tau; else hi = tau;
            if (hi - lo <= eps) break;
            const float nt = tau + (s - 1.0f) / fmaxf(c, 1.0f);   // safeguarded Newton
            tau = (nt > lo && nt < hi) ? nt : 0.5f * (lo + hi);
        }
        const float tau0 = 0.5f * (lo + hi);
        tau_prev = tau0;

        // -------- active-set classification + differentiable tau --------
        float sfree = 0.f, pack = 0.f;   // pack = cfree + 512*cup (exact ints)
        {
            float z;
            z = vv.x - tau0;
            if (z > 0.f && z < MW) { sfree += vv.x; pack += 1.f; } else if (z >= MW) pack += 512.f;
            z = vv.y - tau0;
            if (z > 0.f && z < MW) { sfree += vv.y; pack += 1.f; } else if (z >= MW) pack += 512.f;
            z = vv.z - tau0;
            if (z > 0.f && z < MW) { sfree += vv.z; pack += 1.f; } else if (z >= MW) pack += 512.f;
            z = vv.w - tau0;
            if (z > 0.f && z < MW) { sfree += vv.w; pack += 1.f; } else if (z >= MW) pack += 512.f;
        }
#pragma unroll
        for (int m = 16; m >= 1; m >>= 1) {
            sfree += __shfl_xor_sync(0xffffffffu, sfree, m);
            pack  += __shfl_xor_sync(0xffffffffu, pack,  m);
        }
        const float cup   = floorf(pack * (1.0f / 512.0f));
        const float cfree = pack - 512.0f * cup;
        const float nfree = fmaxf(cfree, 1.0f);
        const float tau_d = (sfree + MW * cup - 1.0f) / nfree;

        // own-element update
        const float z = v - tau0;
        const bool fr = (z > 0.0f) && (z < MW);
        const bool up = (z >= MW);
        const float wn = fr ? (v - tau_d) : (up ? MW : 0.0f);

        const float tn = 0.5f * (1.0f + sqrtf(1.0f + 4.0f * t * t));
        const float yn = wn + ((t - 1.0f) / tn) * (wn - w);
        w = wn;
        y = yn;
        t = tn;

        buf ^= 1;
        ysh[buf][i] = yn;
        __syncthreads();
    }

    out[(size_t)b * N + i] = w;
}

extern "C" void kernel_launch(void* const* d_in, const int* in_sizes, int n_in,
                              void* d_out, int out_size) {
    const float* rets  = (const float*)d_in[0];
    const float* cov   = (const float*)d_in[1];
    const float* gamma = (const float*)d_in[2];
    const float* alpha = (const float*)d_in[3];
    float* out = (float*)d_out;
    (void)in_sizes; (void)n_in; (void)out_size;

    markowitz_kernel<<<B_TOTAL, N>>>(rets, cov, gamma, alpha, out);
}

// round 7
// speedup vs baseline: 2.5940x; 1.2721x over previous
#include <cuda_runtime.h>

#define B_TOTAL 1024
#define N 128
#define MW 1.0f
#define NITERS 300
#define MAX_EVALS 32

typedef unsigned long long u64;

// ---------- packed f32x2 helpers (Blackwell) ----------
__device__ __forceinline__ u64 pack2(float lo, float hi) {
    u64 r; asm("mov.b64 %0, {%1, %2};" : "=l"(r) : "f"(lo), "f"(hi)); return r;
}
__device__ __forceinline__ void unpack2(u64 p, float& lo, float& hi) {
    asm("mov.b64 {%0, %1}, %2;" : "=f"(lo), "=f"(hi) : "l"(p));
}
__device__ __forceinline__ void ffma2(u64& d, u64 a, u64 b) {
    asm("fma.rn.f32x2 %0, %1, %2, %3;" : "=l"(d) : "l"(a), "l"(b), "l"(d));
}
__device__ __forceinline__ u64 fmul2(u64 a, u64 b) {
    u64 r; asm("mul.rn.f32x2 %0, %1, %2;" : "=l"(r) : "l"(a), "l"(b)); return r;
}

__device__ __forceinline__ float wsum(float v) {
#pragma unroll
    for (int m = 16; m >= 1; m >>= 1)
        v += __shfl_xor_sync(0xffffffffu, v, m);
    return v;
}

__global__ __launch_bounds__(128, 3)
void markowitz_kernel(const float* __restrict__ rets,
                      const float* __restrict__ cov,
                      const float* __restrict__ gamma_sqrt,
                      const float* __restrict__ alpha,
                      float* __restrict__ out)
{
    __shared__ __align__(16) float ysh[2][N];
    __shared__ __align__(16) float vsh[N];
    __shared__ float red[4];

    const int b = blockIdx.x;
    const int i = threadIdx.x;
    const int lane = i & 31;

    const float* __restrict__ Cb = cov + (size_t)b * (N * N);

    // ---------------- Phase A: Q = g^2 * C^T C + |alpha| I (packed pairs) ----------------
    u64 qp[N / 2];
#pragma unroll
    for (int j = 0; j < N / 2; ++j) qp[j] = 0ULL;   // {0.f, 0.f}

#pragma unroll 1
    for (int k = 0; k < N; ++k) {
        const float c = Cb[k * N + i];                               // coalesced
        const u64 c2 = pack2(c, c);
        const ulonglong2* __restrict__ rk = (const ulonglong2*)(Cb + k * N);  // broadcast, 16B
#pragma unroll
        for (int j4 = 0; j4 < N / 4; ++j4) {
            ulonglong2 r = rk[j4];
            ffma2(qp[2 * j4 + 0], c2, r.x);
            ffma2(qp[2 * j4 + 1], c2, r.y);
        }
    }

    const float g = gamma_sqrt[b];
    const float g2 = g * g;
    const float aab = fabsf(alpha[b]);

    const u64 g22 = pack2(g2, g2);
#pragma unroll
    for (int j = 0; j < N / 2; ++j) qp[j] = fmul2(qp[j], g22);
    {   // diagonal: q[i] += |alpha|
        float e0, e1; unpack2(qp[i >> 1], e0, e1);
        if (i & 1) e1 += aab; else e0 += aab;
        qp[i >> 1] = pack2(e0, e1);
    }

    // Frobenius norm -> step = 1/(2*||Q||_F)
    u64 f2 = 0ULL;
#pragma unroll
    for (int j = 0; j < N / 2; ++j) ffma2(f2, qp[j], qp[j]);
    float fa, fb; unpack2(f2, fa, fb);
    float fro = wsum(fa + fb);
    if (lane == 0) red[i >> 5] = fro;
    __syncthreads();
    const float totF = (red[0] + red[1]) + (red[2] + red[3]);
    const float step = 1.0f / (2.0f * sqrtf(totF));

    // Fold: qs = 2*step*Q, rs = step*rets
    const float two_step = 2.0f * step;
    const u64 ts2 = pack2(two_step, two_step);
#pragma unroll
    for (int j = 0; j < N / 2; ++j) qp[j] = fmul2(qp[j], ts2);
    const float rs = step * rets[(size_t)b * N + i];

    // ---------------- Phase B: FISTA ----------------
    float w = 1.0f / (float)N;
    float y = w;
    float t = 1.0f;
    float tau_prev = 0.0f;
    int buf = 0;
    ysh[0][i] = y;
    __syncthreads();

#pragma unroll 1
    for (int it = 0; it < NITERS; ++it) {
        // grad step: v = y - (2*step*Q) y + step*rets  (packed matvec)
        const ulonglong2* __restrict__ yv = (const ulonglong2*)ysh[buf];
        u64 d0 = 0ULL, d1 = 0ULL, d2 = 0ULL, d3 = 0ULL;
#pragma unroll
        for (int j4 = 0; j4 < N / 4; j4 += 2) {
            ulonglong2 u0 = yv[j4];
            ulonglong2 u1 = yv[j4 + 1];
            ffma2(d0, qp[2 * j4 + 0], u0.x);
            ffma2(d1, qp[2 * j4 + 1], u0.y);
            ffma2(d2, qp[2 * j4 + 2], u1.x);
            ffma2(d3, qp[2 * j4 + 3], u1.y);
        }
        float p0, p1, p2, p3, p4, p5, p6, p7;
        unpack2(d0, p0, p1); unpack2(d1, p2, p3);
        unpack2(d2, p4, p5); unpack2(d3, p6, p7);
        const float v = y - (((p0 + p1) + (p2 + p3)) + ((p4 + p5) + (p6 + p7))) + rs;
        vsh[i] = v;
        __syncthreads();

        // -------- warp-redundant projection: safeguarded Newton --------
        const float4 vv = ((const float4*)vsh)[lane];

        float mn = fminf(fminf(vv.x, vv.y), fminf(vv.z, vv.w));
        float mx = fmaxf(fmaxf(vv.x, vv.y), fmaxf(vv.z, vv.w));
#pragma unroll
        for (int m = 16; m >= 1; m >>= 1) {
            mn = fminf(mn, __shfl_xor_sync(0xffffffffu, mn, m));
            mx = fmaxf(mx, __shfl_xor_sync(0xffffffffu, mx, m));
        }
        float lo = mn - MW;
        float hi = mx;
        const float eps = 1e-6f * (hi - lo);

        float tau = (tau_prev > lo && tau_prev < hi) ? tau_prev : 0.5f * (lo + hi);
        float s, c;

#pragma unroll 1
        for (int e = 0; e < MAX_EVALS; ++e) {
            const float z0 = __saturatef(vv.x - tau);
            const float z1 = __saturatef(vv.y - tau);
            const float z2 = __saturatef(vv.z - tau);
            const float z3 = __saturatef(vv.w - tau);
            s = (z0 + z1) + (z2 + z3);
            c = ((z0 > 0.f && z0 < 1.f) ? 1.f : 0.f)
              + ((z1 > 0.f && z1 < 1.f) ? 1.f : 0.f)
              + ((z2 > 0.f && z2 < 1.f) ? 1.f : 0.f)
              + ((z3 > 0.f && z3 < 1.f) ? 1.f : 0.f);
#pragma unroll
            for (int m = 16; m >= 1; m >>= 1) {
                s += __shfl_xor_sync(0xffffffffu, s, m);
                c += __shfl_xor_sync(0xffffffffu, c, m);
            }
            if (s > 1.0f) lo = tau; else hi = tau;
            if (s == 1.0f) break;                 // exact root (uniform branch)
            if (hi - lo <= eps) break;
            const float nt = tau + (s - 1.0f) / fmaxf(c, 1.0f);
            tau = (nt > lo && nt < hi) ? nt : 0.5f * (lo + hi);
        }

        // Newton identity == reference's active-set re-derived tau:
        //   tau_d = (sfree + mw*cup - 1)/nfree  ==  tau + (s(tau)-1)/c(tau)
        const float nfree = fmaxf(c, 1.0f);
        const float tau_d = tau + (s - 1.0f) / nfree;
        tau_prev = tau_d;                         // warm start next iteration at the root

        // own-element update (classify against last eval point tau)
        const float z = v - tau;
        const bool fr = (z > 0.0f) && (z < MW);
        const bool up = (z >= MW);
        const float wn = fr ? (v - tau_d) : (up ? MW : 0.0f);

        const float tn = 0.5f * (1.0f + sqrtf(1.0f + 4.0f * t * t));
        const float yn = wn + ((t - 1.0f) / tn) * (wn - w);
        w = wn;
        y = yn;
        t = tn;

        buf ^= 1;
        ysh[buf][i] = yn;
        __syncthreads();
    }

    out[(size_t)b * N + i] = w;
}

extern "C" void kernel_launch(void* const* d_in, const int* in_sizes, int n_in,
                              void* d_out, int out_size) {
    const float* rets  = (const float*)d_in[0];
    const float* cov   = (const float*)d_in[1];
    const float* gamma = (const float*)d_in[2];
    const float* alpha = (const float*)d_in[3];
    float* out = (float*)d_out;
    (void)in_sizes; (void)n_in; (void)out_size;

    markowitz_kernel<<<B_TOTAL, N>>>(rets, cov, gamma, alpha, out);
}